// round 1
// baseline (speedup 1.0000x reference)
#include <cuda_runtime.h>

// Problem shape (fixed by the dataset)
#define BB 256
#define SS 2048
#define HH 128
#define NB 2
#define NTHREADS 512
#define DT 0.1f

typedef unsigned long long ull;

// Packed fp32x2 FMA (Blackwell sm_100+): two fp32 FMAs per instruction.
__device__ __forceinline__ ull ffma2(ull a, ull b, ull c) {
    ull d;
    asm("fma.rn.f32x2 %0, %1, %2, %3;" : "=l"(d) : "l"(a), "l"(b), "l"(c));
    return d;
}

__device__ __forceinline__ float2 unpack2(ull v) {
    float2 r;
    asm("mov.b64 {%0, %1}, %2;" : "=f"(r.x), "=f"(r.y) : "l"(v));
    return r;
}

// sigmoid(x) = 1/(1+exp(-x)); __expf + __fdividef: ~1e-6 rel err, MUFU-based.
__device__ __forceinline__ float fast_sigmoid(float x) {
    return __fdividef(1.0f, 1.0f + __expf(-x));
}

// tanh(x) = 1 - 2/(exp(2x)+1); saturates correctly at +-1 for large |x|.
__device__ __forceinline__ float fast_tanh(float x) {
    return 1.0f - __fdividef(2.0f, __expf(2.0f * x) + 1.0f);
}

// One 128x128 matvec for two batches. W: 8 ulonglong2 (32 fp32 weights) in
// registers for this thread's (h, j in [32q,32q+32)) slice. v0/v1: smem h
// vectors (16B aligned). Result: full dot for row h broadcast to all 4 q lanes.
__device__ __forceinline__ void matvec2(const ulonglong2 (&W)[8],
                                        const float* v0, const float* v1,
                                        int q, float& D0, float& D1) {
    const ulonglong2* p0 = reinterpret_cast<const ulonglong2*>(v0) + q * 8;
    const ulonglong2* p1 = reinterpret_cast<const ulonglong2*>(v1) + q * 8;
    ull a0 = 0ull, a1 = 0ull;
#pragma unroll
    for (int k = 0; k < 8; k++) {
        ulonglong2 h0 = p0[k];
        ulonglong2 h1 = p1[k];
        a0 = ffma2(W[k].x, h0.x, a0);
        a0 = ffma2(W[k].y, h0.y, a0);
        a1 = ffma2(W[k].x, h1.x, a1);
        a1 = ffma2(W[k].y, h1.y, a1);
    }
    float2 f0 = unpack2(a0);
    float2 f1 = unpack2(a1);
    float s0 = f0.x + f0.y;
    float s1 = f1.x + f1.y;
    // reduce over the 4 q-lanes (lanes l, l^1, l^2 share the same h)
    s0 += __shfl_xor_sync(0xffffffffu, s0, 1);
    s0 += __shfl_xor_sync(0xffffffffu, s0, 2);
    s1 += __shfl_xor_sync(0xffffffffu, s1, 1);
    s1 += __shfl_xor_sync(0xffffffffu, s1, 2);
    D0 = s0;
    D1 = s1;
}

__global__ void __launch_bounds__(NTHREADS, 1)
liquid_scan_kernel(const float* __restrict__ x,
                   const float* __restrict__ W_in, const float* __restrict__ b_in,
                   const float* __restrict__ W_rec, const float* __restrict__ b_rec,
                   const float* __restrict__ tau,
                   const float* __restrict__ W_att, const float* __restrict__ b_att,
                   const float* __restrict__ W_ev, const float* __restrict__ b_ev,
                   const float* __restrict__ W_acc, const float* __restrict__ b_acc,
                   const float* __restrict__ W_out, const float* __restrict__ b_out,
                   float* __restrict__ out) {
    __shared__ __align__(16) float xs[NB][SS];     // input rows (16 KB)
    __shared__ __align__(16) float hs[NB][HH];     // hidden state
    __shared__ __align__(16) float hatts[NB][HH];  // h * att   (also reused for final reduce)

    const int tid = threadIdx.x;
    const int h = tid >> 2;   // output row 0..127
    const int q = tid & 3;    // quarter of the K dim
    const int b0 = blockIdx.x * NB;

    // ---- prologue: stage x rows into smem (S/4 == NTHREADS float4s per row)
    {
        const float4* xg0 = reinterpret_cast<const float4*>(x + (size_t)b0 * SS);
        const float4* xg1 = reinterpret_cast<const float4*>(x + (size_t)(b0 + 1) * SS);
        reinterpret_cast<float4*>(xs[0])[tid] = xg0[tid];
        reinterpret_cast<float4*>(xs[1])[tid] = xg1[tid];
    }
    if (tid < HH) { hs[0][tid] = 0.0f; hs[1][tid] = 0.0f; }

    // ---- weights into registers: 3 x 32 fp32 per thread = 96 regs
    ulonglong2 wa[8], wr[8], wc[8];
    {
        const ulonglong2* Wa = reinterpret_cast<const ulonglong2*>(W_att + h * HH + q * 32);
        const ulonglong2* Wr = reinterpret_cast<const ulonglong2*>(W_rec + h * HH + q * 32);
        const ulonglong2* Wc = reinterpret_cast<const ulonglong2*>(W_acc + h * HH + q * 32);
#pragma unroll
        for (int k = 0; k < 8; k++) { wa[k] = Wa[k]; wr[k] = Wr[k]; wc[k] = Wc[k]; }
    }
    const float win  = W_in[h];
    const float bin  = b_in[h];
    const float batt = b_att[h];
    const float brec = b_rec[h];
    const float bacc = b_acc[h];
    const float tc   = fminf(fmaxf(tau[h], 0.1f), 10.0f);
    const float itau = 1.0f / tc;
    const float wev0 = W_ev[0];
    const float wev1 = W_ev[1];
    const float bev  = b_ev[0];

    float acc0 = 0.0f, acc1 = 0.0f;   // accumulator state (identical on all 4 q-lanes)
    float xp0 = 0.0f, xp1 = 0.0f;     // previous x

    __syncthreads();

#pragma unroll 1
    for (int s = 0; s < SS; s++) {
        const float xt0 = xs[0][s];
        const float xt1 = xs[1][s];
        float ew0 = fast_sigmoid(wev0 * xt0 + wev1 * xp0 + bev);
        float ew1 = fast_sigmoid(wev0 * xt1 + wev1 * xp1 + bev);
        if (s == 0) { ew0 = 0.0f; ew1 = 0.0f; }
        xp0 = xt0; xp1 = xt1;
        const float ic0 = fast_tanh(win * xt0 + bin);
        const float ic1 = fast_tanh(win * xt1 + bin);

        // --- attention gate: att = sigmoid(h @ W_att^T + b_att)
        float d0, d1;
        matvec2(wa, hs[0], hs[1], q, d0, d1);
        const float att0 = fast_sigmoid(d0 + batt);
        const float att1 = fast_sigmoid(d1 + batt);
        const float hold0 = hs[0][h];
        const float hold1 = hs[1][h];
        if (q == 0) {
            hatts[0][h] = hold0 * att0;
            hatts[1][h] = hold1 * att1;
        }
        __syncthreads();

        // --- recurrence: rec = tanh((h*att) @ W_rec^T + b_rec); h update
        matvec2(wr, hatts[0], hatts[1], q, d0, d1);
        const float rec0 = fast_tanh(d0 + brec);
        const float rec1 = fast_tanh(d1 + brec);
        const float hn0 = hold0 + DT * ((-hold0 + ic0 + rec0) * itau) * (1.0f + ew0);
        const float hn1 = hold1 + DT * ((-hold1 + ic1 + rec1) * itau) * (1.0f + ew1);
        if (q == 0) {
            hs[0][h] = hn0;
            hs[1][h] = hn1;
        }
        __syncthreads();

        // --- accumulator: acc = 0.9 acc + 0.1 tanh(h_new @ W_acc^T + b_acc) * ew
        matvec2(wc, hs[0], hs[1], q, d0, d1);
        acc0 = 0.9f * acc0 + 0.1f * fast_tanh(d0 + bacc) * ew0;
        acc1 = 0.9f * acc1 + 0.1f * fast_tanh(d1 + bacc) * ew1;
    }

    // ---- epilogue: out[b] = (h_f + acc_f) . W_out + b_out
    if (q == 0) {
        hatts[0][h] = hs[0][h] + acc0;
        hatts[1][h] = hs[1][h] + acc1;
    }
    __syncthreads();
    const int w = tid >> 5, l = tid & 31;
    if (w < NB) {
        float p = 0.0f;
#pragma unroll
        for (int i = 0; i < HH / 32; i++) p += hatts[w][l + 32 * i] * W_out[l + 32 * i];
#pragma unroll
        for (int o = 16; o; o >>= 1) p += __shfl_xor_sync(0xffffffffu, p, o);
        if (l == 0) out[b0 + w] = p + b_out[0];
    }
}

// event_weights[b,s] = sigmoid(w0*x[b,s] + w1*x[b,s-1] + b) for s>0, else 0.
__global__ void ew_kernel(const float* __restrict__ x,
                          const float* __restrict__ W_ev,
                          const float* __restrict__ b_ev,
                          float* __restrict__ out_ew) {
    const int i = blockIdx.x * blockDim.x + threadIdx.x;
    if (i >= BB * SS) return;
    const int s = i & (SS - 1);
    float e = 0.0f;
    if (s > 0) {
        e = fast_sigmoid(W_ev[0] * x[i] + W_ev[1] * x[i - 1] + b_ev[0]);
    }
    out_ew[i] = e;
}

extern "C" void kernel_launch(void* const* d_in, const int* in_sizes, int n_in,
                              void* d_out, int out_size) {
    const float* x     = (const float*)d_in[0];
    const float* W_in  = (const float*)d_in[1];
    const float* b_in  = (const float*)d_in[2];
    const float* W_rec = (const float*)d_in[3];
    const float* b_rec = (const float*)d_in[4];
    const float* tau   = (const float*)d_in[5];
    const float* W_att = (const float*)d_in[6];
    const float* b_att = (const float*)d_in[7];
    const float* W_ev  = (const float*)d_in[8];
    const float* b_ev  = (const float*)d_in[9];
    const float* W_acc = (const float*)d_in[10];
    const float* b_acc = (const float*)d_in[11];
    const float* W_out = (const float*)d_in[12];
    const float* b_out = (const float*)d_in[13];
    float* out = (float*)d_out;

    // Output layout: [B] final outputs, then [B*S] event weights.
    if (out_size >= BB + BB * SS) {
        ew_kernel<<<(BB * SS + 255) / 256, 256>>>(x, W_ev, b_ev, out + BB);
    }
    liquid_scan_kernel<<<BB / NB, NTHREADS>>>(x, W_in, b_in, W_rec, b_rec, tau,
                                              W_att, b_att, W_ev, b_ev,
                                              W_acc, b_acc, W_out, b_out, out);
}

// round 2
// speedup vs baseline: 1.2962x; 1.2962x over previous
#include <cuda_runtime.h>

// Problem shape (fixed by the dataset)
#define BB 256
#define SS 2048
#define HH 128
#define NB 2
#define NTHREADS 512
#define DT 0.1f

typedef unsigned long long ull;

// Packed fp32x2 FMA (Blackwell): two fp32 MACs per instruction.
__device__ __forceinline__ ull ffma2(ull a, ull b, ull c) {
    ull d;
    asm("fma.rn.f32x2 %0, %1, %2, %3;" : "=l"(d) : "l"(a), "l"(b), "l"(c));
    return d;
}
__device__ __forceinline__ float2 unpack2(ull v) {
    float2 r;
    asm("mov.b64 {%0, %1}, %2;" : "=f"(r.x), "=f"(r.y) : "l"(v));
    return r;
}
// Single-MUFU activations (MUFU.TANH, abs err ~2e-5 — well inside 1e-3 tol).
__device__ __forceinline__ float tanha(float x) {
    float t; asm("tanh.approx.f32 %0, %1;" : "=f"(t) : "f"(x)); return t;
}
__device__ __forceinline__ float siga(float x) {
    float t; asm("tanh.approx.f32 %0, %1;" : "=f"(t) : "f"(0.5f * x));
    return 0.5f * t + 0.5f;
}
// Reduce a packed fp32x2 accumulator across the 4 q-lanes of a row.
__device__ __forceinline__ float redq(ull a) {
    float2 f = unpack2(a);
    float s = f.x + f.y;
    s += __shfl_xor_sync(0xffffffffu, s, 1);
    s += __shfl_xor_sync(0xffffffffu, s, 2);
    return s;
}

__global__ void __launch_bounds__(NTHREADS, 1)
liquid_scan_kernel(const float* __restrict__ x,
                   const float* __restrict__ W_in, const float* __restrict__ b_in,
                   const float* __restrict__ W_rec, const float* __restrict__ b_rec,
                   const float* __restrict__ tau,
                   const float* __restrict__ W_att, const float* __restrict__ b_att,
                   const float* __restrict__ W_ev, const float* __restrict__ b_ev,
                   const float* __restrict__ W_acc, const float* __restrict__ b_acc,
                   const float* __restrict__ W_out, const float* __restrict__ b_out,
                   float* __restrict__ out) {
    __shared__ __align__(16) float xs[NB][SS];     // input rows (16 KB)
    __shared__ __align__(16) float ews[NB][SS];    // event weights (16 KB)
    __shared__ __align__(16) float hs[NB][HH];     // hidden state
    __shared__ __align__(16) float hatts[NB][HH];  // h * att (reused in epilogue)

    const int tid = threadIdx.x;
    const int h = tid >> 2;   // output row 0..127
    const int q = tid & 3;    // quarter of the K dim
    const int b0 = blockIdx.x * NB;

    // ---- stage x rows into smem
    {
        const float4* xg0 = reinterpret_cast<const float4*>(x + (size_t)b0 * SS);
        const float4* xg1 = reinterpret_cast<const float4*>(x + (size_t)(b0 + 1) * SS);
        reinterpret_cast<float4*>(xs[0])[tid] = xg0[tid];
        reinterpret_cast<float4*>(xs[1])[tid] = xg1[tid];
    }
    if (tid < HH) { hs[0][tid] = 0.0f; hs[1][tid] = 0.0f; }
    __syncthreads();

    // ---- precompute event weights into smem AND the event_weights output
    {
        const float wev0 = W_ev[0], wev1 = W_ev[1], bev = b_ev[0];
        float* out_ew = out + BB;
#pragma unroll
        for (int k = 0; k < SS / NTHREADS; k++) {
            const int s = tid + k * NTHREADS;
#pragma unroll
            for (int b = 0; b < NB; b++) {
                float e = 0.0f;
                if (s > 0) e = siga(wev0 * xs[b][s] + wev1 * xs[b][s - 1] + bev);
                ews[b][s] = e;
                out_ew[(size_t)(b0 + b) * SS + s] = e;
            }
        }
    }

    // ---- weights into registers: 3 x 32 fp32 per thread = 96 regs
    ulonglong2 wa[8], wr[8], wc[8];
    {
        const ulonglong2* Wa = reinterpret_cast<const ulonglong2*>(W_att + h * HH + q * 32);
        const ulonglong2* Wr = reinterpret_cast<const ulonglong2*>(W_rec + h * HH + q * 32);
        const ulonglong2* Wc = reinterpret_cast<const ulonglong2*>(W_acc + h * HH + q * 32);
#pragma unroll
        for (int k = 0; k < 8; k++) { wa[k] = Wa[k]; wr[k] = Wr[k]; wc[k] = Wc[k]; }
    }
    const float win  = W_in[h];
    const float bin  = b_in[h];
    const float batt = b_att[h];
    const float brec = b_rec[h];
    const float bacc = b_acc[h];
    const float itau = 1.0f / fminf(fmaxf(tau[h], 0.1f), 10.0f);

    float acc0 = 0.0f, acc1 = 0.0f;  // accumulator state (replicated on q-lanes)
    float ewp0 = 0.0f, ewp1 = 0.0f;  // ew of previous step (pipelined acc update)

    __syncthreads();

#pragma unroll 1
    for (int s = 0; s < SS; s++) {
        // ---- phase A: fused att + acc matvec on h_s (shared LDS of h vector)
        const ulonglong2* p0 = reinterpret_cast<const ulonglong2*>(hs[0]) + q * 8;
        const ulonglong2* p1 = reinterpret_cast<const ulonglong2*>(hs[1]) + q * 8;
        ull aa0 = 0, aa1 = 0, ac0 = 0, ac1 = 0;
#pragma unroll
        for (int k = 0; k < 8; k++) {
            const ulonglong2 h0 = p0[k];
            const ulonglong2 h1 = p1[k];
            aa0 = ffma2(wa[k].x, h0.x, aa0); aa0 = ffma2(wa[k].y, h0.y, aa0);
            aa1 = ffma2(wa[k].x, h1.x, aa1); aa1 = ffma2(wa[k].y, h1.y, aa1);
            ac0 = ffma2(wc[k].x, h0.x, ac0); ac0 = ffma2(wc[k].y, h0.y, ac0);
            ac1 = ffma2(wc[k].x, h1.x, ac1); ac1 = ffma2(wc[k].y, h1.y, ac1);
        }
        const float att0 = siga(redq(aa0) + batt);
        const float att1 = siga(redq(aa1) + batt);
        // acc update for step s-1 uses tanh(W_acc @ h_s) and ew_{s-1}
        acc0 = 0.9f * acc0 + 0.1f * tanha(redq(ac0) + bacc) * ewp0;
        acc1 = 0.9f * acc1 + 0.1f * tanha(redq(ac1) + bacc) * ewp1;

        const float hold0 = hs[0][h];
        const float hold1 = hs[1][h];
        if (q == 0) {
            hatts[0][h] = hold0 * att0;
            hatts[1][h] = hold1 * att1;
        }
        __syncthreads();

        // ---- phase B: recurrence matvec on h*att, then state update
        const ulonglong2* r0 = reinterpret_cast<const ulonglong2*>(hatts[0]) + q * 8;
        const ulonglong2* r1 = reinterpret_cast<const ulonglong2*>(hatts[1]) + q * 8;
        ull ar0 = 0, ar1 = 0;
#pragma unroll
        for (int k = 0; k < 8; k++) {
            const ulonglong2 h0 = r0[k];
            const ulonglong2 h1 = r1[k];
            ar0 = ffma2(wr[k].x, h0.x, ar0); ar0 = ffma2(wr[k].y, h0.y, ar0);
            ar1 = ffma2(wr[k].x, h1.x, ar1); ar1 = ffma2(wr[k].y, h1.y, ar1);
        }
        const float rec0 = tanha(redq(ar0) + brec);
        const float rec1 = tanha(redq(ar1) + brec);
        const float ic0 = tanha(win * xs[0][s] + bin);
        const float ic1 = tanha(win * xs[1][s] + bin);
        const float ew0 = ews[0][s];
        const float ew1 = ews[1][s];
        const float hn0 = hold0 + DT * ((ic0 + rec0 - hold0) * itau) * (1.0f + ew0);
        const float hn1 = hold1 + DT * ((ic1 + rec1 - hold1) * itau) * (1.0f + ew1);
        if (q == 0) {
            hs[0][h] = hn0;
            hs[1][h] = hn1;
        }
        ewp0 = ew0;
        ewp1 = ew1;
        __syncthreads();
    }

    // ---- trailing acc update: tanh(W_acc @ h_S) with ew_{S-1}
    {
        const ulonglong2* p0 = reinterpret_cast<const ulonglong2*>(hs[0]) + q * 8;
        const ulonglong2* p1 = reinterpret_cast<const ulonglong2*>(hs[1]) + q * 8;
        ull ac0 = 0, ac1 = 0;
#pragma unroll
        for (int k = 0; k < 8; k++) {
            const ulonglong2 h0 = p0[k];
            const ulonglong2 h1 = p1[k];
            ac0 = ffma2(wc[k].x, h0.x, ac0); ac0 = ffma2(wc[k].y, h0.y, ac0);
            ac1 = ffma2(wc[k].x, h1.x, ac1); ac1 = ffma2(wc[k].y, h1.y, ac1);
        }
        acc0 = 0.9f * acc0 + 0.1f * tanha(redq(ac0) + bacc) * ewp0;
        acc1 = 0.9f * acc1 + 0.1f * tanha(redq(ac1) + bacc) * ewp1;
    }

    // ---- epilogue: out[b] = (h_f + acc_f) . W_out + b_out
    if (q == 0) {
        hatts[0][h] = hs[0][h] + acc0;
        hatts[1][h] = hs[1][h] + acc1;
    }
    __syncthreads();
    const int w = tid >> 5, l = tid & 31;
    if (w < NB) {
        float p = 0.0f;
#pragma unroll
        for (int i = 0; i < HH / 32; i++) p += hatts[w][l + 32 * i] * W_out[l + 32 * i];
#pragma unroll
        for (int o = 16; o; o >>= 1) p += __shfl_xor_sync(0xffffffffu, p, o);
        if (l == 0) out[b0 + w] = p + b_out[0];
    }
}

extern "C" void kernel_launch(void* const* d_in, const int* in_sizes, int n_in,
                              void* d_out, int out_size) {
    const float* x     = (const float*)d_in[0];
    const float* W_in  = (const float*)d_in[1];
    const float* b_in  = (const float*)d_in[2];
    const float* W_rec = (const float*)d_in[3];
    const float* b_rec = (const float*)d_in[4];
    const float* tau   = (const float*)d_in[5];
    const float* W_att = (const float*)d_in[6];
    const float* b_att = (const float*)d_in[7];
    const float* W_ev  = (const float*)d_in[8];
    const float* b_ev  = (const float*)d_in[9];
    const float* W_acc = (const float*)d_in[10];
    const float* b_acc = (const float*)d_in[11];
    const float* W_out = (const float*)d_in[12];
    const float* b_out = (const float*)d_in[13];
    float* out = (float*)d_out;

    liquid_scan_kernel<<<BB / NB, NTHREADS>>>(x, W_in, b_in, W_rec, b_rec, tau,
                                              W_att, b_att, W_ev, b_ev,
                                              W_acc, b_acc, W_out, b_out, out);
}

// round 3
// speedup vs baseline: 4.2406x; 3.2714x over previous
#include <cuda_runtime.h>

// Problem shape (fixed by the dataset)
#define BB 256
#define SS 2048
#define HH 128
#define NB 2
#define NTHREADS 512
#define DT 0.1f
#define PAD 36           // floats per 32-float q-chunk (16B pad kills 4-way bank conflict)
#define HPAD (4 * PAD)   // 144 floats per padded state vector

typedef unsigned long long ull;

// Packed fp32x2 FMA (Blackwell): two fp32 MACs per instruction.
__device__ __forceinline__ ull ffma2(ull a, ull b, ull c) {
    ull d;
    asm("fma.rn.f32x2 %0, %1, %2, %3;" : "=l"(d) : "l"(a), "l"(b), "l"(c));
    return d;
}
__device__ __forceinline__ float tanha(float x) {
    float t; asm("tanh.approx.f32 %0, %1;" : "=f"(t) : "f"(x)); return t;
}
// Reduce packed fp32x2 accumulator across the 4 q-lanes of a row (same h).
__device__ __forceinline__ float redq(ull a) {
    float lo, hi;
    asm("mov.b64 {%0, %1}, %2;" : "=f"(lo), "=f"(hi) : "l"(a));
    float s = lo + hi;
    s += __shfl_xor_sync(0xffffffffu, s, 1);
    s += __shfl_xor_sync(0xffffffffu, s, 2);
    return s;
}

__global__ void __launch_bounds__(NTHREADS, 1)
liquid_scan_kernel(const float* __restrict__ x,
                   const float* __restrict__ W_in, const float* __restrict__ b_in,
                   const float* __restrict__ W_rec, const float* __restrict__ b_rec,
                   const float* __restrict__ tau,
                   const float* __restrict__ W_att, const float* __restrict__ b_att,
                   const float* __restrict__ W_ev, const float* __restrict__ b_ev,
                   const float* __restrict__ W_acc, const float* __restrict__ b_acc,
                   const float* __restrict__ W_out, const float* __restrict__ b_out,
                   float* __restrict__ out) {
    __shared__ __align__(16) float xs[NB][SS];       // input rows
    __shared__ __align__(16) float ews[NB][SS];      // event weights
    __shared__ __align__(16) float hs[NB][HPAD];     // hidden state (padded chunks)
    __shared__ __align__(16) float hatts[NB][HPAD];  // h * att (padded chunks)

    const int tid = threadIdx.x;
    const int h = tid >> 2;       // output row 0..127
    const int q = tid & 3;        // quarter of the K dim / lane role
    const int p = q & 1;          // batch parity for this lane's role
    const int b0 = blockIdx.x * NB;
    const int vqf = q * PAD;                          // padded chunk base (floats)
    const int hoff = (h >> 5) * PAD + (h & 31);       // padded scalar index for h

    // ---- stage x rows into smem
    {
        const float4* xg0 = reinterpret_cast<const float4*>(x + (size_t)b0 * SS);
        const float4* xg1 = reinterpret_cast<const float4*>(x + (size_t)(b0 + 1) * SS);
        reinterpret_cast<float4*>(xs[0])[tid] = xg0[tid];
        reinterpret_cast<float4*>(xs[1])[tid] = xg1[tid];
    }
    if (tid < HPAD) { hs[0][tid] = 0.0f; hs[1][tid] = 0.0f; }
    __syncthreads();

    // ---- precompute event weights into smem AND the event_weights output
    {
        const float wev0 = W_ev[0], wev1 = W_ev[1], bev = b_ev[0];
        float* out_ew = out + BB;
#pragma unroll
        for (int k = 0; k < SS / NTHREADS; k++) {
            const int s = tid + k * NTHREADS;
#pragma unroll
            for (int b = 0; b < NB; b++) {
                float e = 0.0f;
                if (s > 0) {
                    float t = tanha(0.5f * (wev0 * xs[b][s] + wev1 * xs[b][s - 1] + bev));
                    e = fmaf(0.5f, t, 0.5f);
                }
                ews[b][s] = e;
                out_ew[(size_t)(b0 + b) * SS + s] = e;
            }
        }
    }

    // ---- weights into registers: 3 x 32 fp32 per thread = 96 regs
    ulonglong2 wa[8], wr[8], wc[8];
    {
        const ulonglong2* Wa = reinterpret_cast<const ulonglong2*>(W_att + h * HH + q * 32);
        const ulonglong2* Wr = reinterpret_cast<const ulonglong2*>(W_rec + h * HH + q * 32);
        const ulonglong2* Wc = reinterpret_cast<const ulonglong2*>(W_acc + h * HH + q * 32);
#pragma unroll
        for (int k = 0; k < 8; k++) { wa[k] = Wa[k]; wr[k] = Wr[k]; wc[k] = Wc[k]; }
    }
    // Lane-role-folded scalars.
    const float pA_bias = (q < 2) ? b_att[h] : b_acc[h];   // phase A bias
    const float brec = b_rec[h];
    const float win  = W_in[h];
    const float bin  = b_in[h];
    const float itau = 1.0f / fminf(fmaxf(tau[h], 0.1f), 10.0f);

    float accq = 0.0f;   // acc state: q2 holds acc[batch0], q3 holds acc[batch1]
    float ewpq = 0.0f;   // previous step's event weight for this lane's batch

    __syncthreads();

#pragma unroll 1
    for (int s = 0; s < SS; s++) {
        // ---- phase A: att + acc matvecs on h_s, per-batch passes
        ull aa = 0, ac = 0;
#pragma unroll
        for (int k = 0; k < 8; k++) {
            const ulonglong2 hv = *reinterpret_cast<const ulonglong2*>(&hs[0][vqf + 4 * k]);
            aa = ffma2(wa[k].x, hv.x, aa); aa = ffma2(wa[k].y, hv.y, aa);
            ac = ffma2(wc[k].x, hv.x, ac); ac = ffma2(wc[k].y, hv.y, ac);
        }
        const float A0 = redq(aa), C0 = redq(ac);
        aa = 0; ac = 0;
#pragma unroll
        for (int k = 0; k < 8; k++) {
            const ulonglong2 hv = *reinterpret_cast<const ulonglong2*>(&hs[1][vqf + 4 * k]);
            aa = ffma2(wa[k].x, hv.x, aa); aa = ffma2(wa[k].y, hv.y, aa);
            ac = ffma2(wc[k].x, hv.x, ac); ac = ffma2(wc[k].y, hv.y, ac);
        }
        const float A1 = redq(aa), C1 = redq(ac);

        // lane roles: q0->att(b0), q1->att(b1), q2->acc-tanh(b0), q3->acc-tanh(b1)
        const float inA = ((q & 2) ? (p ? C1 : C0) : (p ? A1 : A0)) + pA_bias;
        const float tA = tanha((q < 2) ? 0.5f * inA : inA);
        const float vA = (q < 2) ? fmaf(0.5f, tA, 0.5f) : tA;

        const float hold = hs[p][hoff];          // this lane's batch old h
        if (q < 2) hatts[p][hoff] = hold * vA;   // q0 writes b0, q1 writes b1
        accq = 0.9f * accq + 0.1f * vA * ewpq;   // meaningful on q2/q3 only
        __syncthreads();

        // ---- phase B: recurrence matvec on h*att, state update
        ull ar0 = 0, ar1 = 0;
#pragma unroll
        for (int k = 0; k < 8; k++) {
            const ulonglong2 h0 = *reinterpret_cast<const ulonglong2*>(&hatts[0][vqf + 4 * k]);
            const ulonglong2 h1 = *reinterpret_cast<const ulonglong2*>(&hatts[1][vqf + 4 * k]);
            ar0 = ffma2(wr[k].x, h0.x, ar0); ar0 = ffma2(wr[k].y, h0.y, ar0);
            ar1 = ffma2(wr[k].x, h1.x, ar1); ar1 = ffma2(wr[k].y, h1.y, ar1);
        }
        const float R0 = redq(ar0), R1 = redq(ar1);

        const float xq = xs[p][s];
        const float ewq = ews[p][s];
        // lane roles: q0->rec(b0), q1->rec(b1), q2->ic(b0), q3->ic(b1)
        const float inB = (q & 2) ? fmaf(win, xq, bin) : ((p ? R1 : R0) + brec);
        const float tB = tanha(inB);
        const float icx = __shfl_xor_sync(0xffffffffu, tB, 2);  // q0<-ic0, q1<-ic1
        const float hn = hold + DT * ((icx + tB - hold) * itau) * (1.0f + ewq);
        if (q < 2) hs[p][hoff] = hn;             // q0 writes b0, q1 writes b1
        ewpq = ewq;
        __syncthreads();
    }

    // ---- trailing acc update: tanh(W_acc @ h_S) with ew_{S-1}
    {
        ull ac0 = 0, ac1 = 0;
#pragma unroll
        for (int k = 0; k < 8; k++) {
            const ulonglong2 h0 = *reinterpret_cast<const ulonglong2*>(&hs[0][vqf + 4 * k]);
            const ulonglong2 h1 = *reinterpret_cast<const ulonglong2*>(&hs[1][vqf + 4 * k]);
            ac0 = ffma2(wc[k].x, h0.x, ac0); ac0 = ffma2(wc[k].y, h0.y, ac0);
            ac1 = ffma2(wc[k].x, h1.x, ac1); ac1 = ffma2(wc[k].y, h1.y, ac1);
        }
        const float C0 = redq(ac0), C1 = redq(ac1);
        const float t = tanha((p ? C1 : C0) + pA_bias);  // valid on q2/q3 (bias=bacc)
        accq = 0.9f * accq + 0.1f * t * ewpq;
    }

    // ---- epilogue: out[b] = (h_f + acc_f) . W_out + b_out
    if (q & 2) hatts[p][hoff] = accq;   // q2 -> acc[b0], q3 -> acc[b1]
    __syncthreads();
    const int w = tid >> 5, l = tid & 31;
    if (w < NB) {
        float pacc = 0.0f;
#pragma unroll
        for (int i = 0; i < HH / 32; i++) {
            const int jo = i * PAD + l;
            pacc += (hs[w][jo] + hatts[w][jo]) * W_out[l + 32 * i];
        }
#pragma unroll
        for (int o = 16; o; o >>= 1) pacc += __shfl_xor_sync(0xffffffffu, pacc, o);
        if (l == 0) out[b0 + w] = pacc + b_out[0];
    }
}

extern "C" void kernel_launch(void* const* d_in, const int* in_sizes, int n_in,
                              void* d_out, int out_size) {
    const float* x     = (const float*)d_in[0];
    const float* W_in  = (const float*)d_in[1];
    const float* b_in  = (const float*)d_in[2];
    const float* W_rec = (const float*)d_in[3];
    const float* b_rec = (const float*)d_in[4];
    const float* tau   = (const float*)d_in[5];
    const float* W_att = (const float*)d_in[6];
    const float* b_att = (const float*)d_in[7];
    const float* W_ev  = (const float*)d_in[8];
    const float* b_ev  = (const float*)d_in[9];
    const float* W_acc = (const float*)d_in[10];
    const float* b_acc = (const float*)d_in[11];
    const float* W_out = (const float*)d_in[12];
    const float* b_out = (const float*)d_in[13];
    float* out = (float*)d_out;

    liquid_scan_kernel<<<BB / NB, NTHREADS>>>(x, W_in, b_in, W_rec, b_rec, tau,
                                              W_att, b_att, W_ev, b_ev,
                                              W_acc, b_acc, W_out, b_out, out);
}

// round 4
// speedup vs baseline: 5.9159x; 1.3951x over previous
#include <cuda_runtime.h>

// Problem shape (fixed by the dataset)
#define BB 256
#define SS 2048
#define HH 128
#define NB 2
#define NTHREADS 512
#define DT 0.1f
#define PAD 36           // floats per 32-float chunk (16B pad kills bank conflicts)
#define HPAD (4 * PAD)   // 144 floats per padded state vector

typedef unsigned long long ull;

// Packed fp32x2 FMA (Blackwell): two fp32 MACs per instruction.
__device__ __forceinline__ ull ffma2(ull a, ull b, ull c) {
    ull d;
    asm("fma.rn.f32x2 %0, %1, %2, %3;" : "=l"(d) : "l"(a), "l"(b), "l"(c));
    return d;
}
__device__ __forceinline__ float tanha(float x) {
    float t; asm("tanh.approx.f32 %0, %1;" : "=f"(t) : "f"(x)); return t;
}

// Reduce two packed row-partials (rows r0, r1 of this thread's group) across
// the 8-lane column group. Returns the full dot for THIS lane's row
// (row = 2g + bit2), replicated over the 4 q-lanes.
__device__ __forceinline__ float redq2(ull a0, ull a1, bool hiRow) {
    float l0, h0, l1, h1;
    asm("mov.b64 {%0, %1}, %2;" : "=f"(l0), "=f"(h0) : "l"(a0));
    asm("mov.b64 {%0, %1}, %2;" : "=f"(l1), "=f"(h1) : "l"(a1));
    const float s0 = l0 + h0;
    const float s1 = l1 + h1;
    // xor-4 exchange: low lanes keep row0 (send row1 partial), high lanes keep row1.
    const float x = hiRow ? s0 : s1;
    const float r = __shfl_xor_sync(0xffffffffu, x, 4);
    float s = (hiRow ? s1 : s0) + r;
    s += __shfl_xor_sync(0xffffffffu, s, 2);
    s += __shfl_xor_sync(0xffffffffu, s, 1);
    return s;
}

__global__ void __launch_bounds__(NTHREADS, 1)
liquid_scan_kernel(const float* __restrict__ x,
                   const float* __restrict__ W_in, const float* __restrict__ b_in,
                   const float* __restrict__ W_rec, const float* __restrict__ b_rec,
                   const float* __restrict__ tau,
                   const float* __restrict__ W_att, const float* __restrict__ b_att,
                   const float* __restrict__ W_ev, const float* __restrict__ b_ev,
                   const float* __restrict__ W_acc, const float* __restrict__ b_acc,
                   const float* __restrict__ W_out, const float* __restrict__ b_out,
                   float* __restrict__ out) {
    __shared__ __align__(16) float xs[NB][SS];       // input rows
    __shared__ __align__(16) float ews[NB][SS];      // event weights
    __shared__ __align__(16) float hs[NB][HPAD];     // hidden state (padded chunks)
    __shared__ __align__(16) float hatts[NB][HPAD];  // h * att (padded chunks)

    const int tid = threadIdx.x;
    const int g  = tid >> 3;      // row-pair group: rows 2g, 2g+1
    const int c  = tid & 7;       // 16-col block index within the row group
    const int h  = tid >> 2;      // row this lane owns after reduction (= 2g + bit2)
    const int q  = tid & 3;       // lane role
    const int p  = q & 1;         // batch parity for this lane's role
    const bool hiRow = (tid >> 2) & 1;
    const int b0 = blockIdx.x * NB;
    const int vbase = 16 * c + 4 * (c >> 1);          // padded float offset of col block
    const int hoff = (h >> 5) * PAD + (h & 31);       // padded scalar index for row h

    // ---- stage x rows into smem
    {
        const float4* xg0 = reinterpret_cast<const float4*>(x + (size_t)b0 * SS);
        const float4* xg1 = reinterpret_cast<const float4*>(x + (size_t)(b0 + 1) * SS);
        reinterpret_cast<float4*>(xs[0])[tid] = xg0[tid];
        reinterpret_cast<float4*>(xs[1])[tid] = xg1[tid];
    }
    if (tid < HPAD) { hs[0][tid] = 0.0f; hs[1][tid] = 0.0f; }
    __syncthreads();

    // ---- precompute event weights into smem AND the event_weights output
    {
        const float wev0 = W_ev[0], wev1 = W_ev[1], bev = b_ev[0];
        float* out_ew = out + BB;
#pragma unroll
        for (int k = 0; k < SS / NTHREADS; k++) {
            const int s = tid + k * NTHREADS;
#pragma unroll
            for (int b = 0; b < NB; b++) {
                float e = 0.0f;
                if (s > 0) {
                    float t = tanha(0.5f * (wev0 * xs[b][s] + wev1 * xs[b][s - 1] + bev));
                    e = fmaf(0.5f, t, 0.5f);
                }
                ews[b][s] = e;
                out_ew[(size_t)(b0 + b) * SS + s] = e;
            }
        }
    }

    // ---- weights into registers: 3 mats x 2 rows x 16 cols = 96 fp32
    ulonglong2 wa[2][4], wr[2][4], wc[2][4];
#pragma unroll
    for (int r = 0; r < 2; r++) {
        const int row = 2 * g + r;
        const ulonglong2* Wa = reinterpret_cast<const ulonglong2*>(W_att + row * HH + 16 * c);
        const ulonglong2* Wr = reinterpret_cast<const ulonglong2*>(W_rec + row * HH + 16 * c);
        const ulonglong2* Wc = reinterpret_cast<const ulonglong2*>(W_acc + row * HH + 16 * c);
#pragma unroll
        for (int k = 0; k < 4; k++) { wa[r][k] = Wa[k]; wr[r][k] = Wr[k]; wc[r][k] = Wc[k]; }
    }
    // Lane-role-folded scalars.
    const float pA_bias = (q < 2) ? b_att[h] : b_acc[h];   // phase A bias
    const float brec = b_rec[h];
    const float win  = W_in[h];
    const float bin  = b_in[h];
    const float itau = 1.0f / fminf(fmaxf(tau[h], 0.1f), 10.0f);

    float accq = 0.0f;   // acc state: q2 holds acc[batch0], q3 holds acc[batch1]
    float ewpq = 0.0f;   // previous step's event weight for this lane's batch

    __syncthreads();

#pragma unroll 1
    for (int s = 0; s < SS; s++) {
        // ---- phase A: att + acc matvecs on h_s, batch-sequential
        float A0, C0, A1, C1;
        {
            ull aa0 = 0, aa1 = 0, ac0 = 0, ac1 = 0;
#pragma unroll
            for (int k = 0; k < 4; k++) {
                const ulonglong2 hv = *reinterpret_cast<const ulonglong2*>(&hs[0][vbase + 4 * k]);
                aa0 = ffma2(wa[0][k].x, hv.x, aa0); aa0 = ffma2(wa[0][k].y, hv.y, aa0);
                aa1 = ffma2(wa[1][k].x, hv.x, aa1); aa1 = ffma2(wa[1][k].y, hv.y, aa1);
                ac0 = ffma2(wc[0][k].x, hv.x, ac0); ac0 = ffma2(wc[0][k].y, hv.y, ac0);
                ac1 = ffma2(wc[1][k].x, hv.x, ac1); ac1 = ffma2(wc[1][k].y, hv.y, ac1);
            }
            A0 = redq2(aa0, aa1, hiRow);
            C0 = redq2(ac0, ac1, hiRow);
        }
        {
            ull aa0 = 0, aa1 = 0, ac0 = 0, ac1 = 0;
#pragma unroll
            for (int k = 0; k < 4; k++) {
                const ulonglong2 hv = *reinterpret_cast<const ulonglong2*>(&hs[1][vbase + 4 * k]);
                aa0 = ffma2(wa[0][k].x, hv.x, aa0); aa0 = ffma2(wa[0][k].y, hv.y, aa0);
                aa1 = ffma2(wa[1][k].x, hv.x, aa1); aa1 = ffma2(wa[1][k].y, hv.y, aa1);
                ac0 = ffma2(wc[0][k].x, hv.x, ac0); ac0 = ffma2(wc[0][k].y, hv.y, ac0);
                ac1 = ffma2(wc[1][k].x, hv.x, ac1); ac1 = ffma2(wc[1][k].y, hv.y, ac1);
            }
            A1 = redq2(aa0, aa1, hiRow);
            C1 = redq2(ac0, ac1, hiRow);
        }

        // lane roles: q0->att(b0), q1->att(b1), q2->acc-tanh(b0), q3->acc-tanh(b1)
        const float inA = ((q & 2) ? (p ? C1 : C0) : (p ? A1 : A0)) + pA_bias;
        const float tA = tanha((q < 2) ? 0.5f * inA : inA);
        const float vA = (q < 2) ? fmaf(0.5f, tA, 0.5f) : tA;

        const float hold = hs[p][hoff];          // this lane's batch old h
        if (q < 2) hatts[p][hoff] = hold * vA;   // q0 writes b0, q1 writes b1
        accq = 0.9f * accq + 0.1f * vA * ewpq;   // meaningful on q2/q3 only
        __syncthreads();

        // ---- phase B: recurrence matvec on h*att, state update
        float R0, R1;
        {
            ull ar0 = 0, ar1 = 0;
#pragma unroll
            for (int k = 0; k < 4; k++) {
                const ulonglong2 hv = *reinterpret_cast<const ulonglong2*>(&hatts[0][vbase + 4 * k]);
                ar0 = ffma2(wr[0][k].x, hv.x, ar0); ar0 = ffma2(wr[0][k].y, hv.y, ar0);
                ar1 = ffma2(wr[1][k].x, hv.x, ar1); ar1 = ffma2(wr[1][k].y, hv.y, ar1);
            }
            R0 = redq2(ar0, ar1, hiRow);
        }
        {
            ull ar0 = 0, ar1 = 0;
#pragma unroll
            for (int k = 0; k < 4; k++) {
                const ulonglong2 hv = *reinterpret_cast<const ulonglong2*>(&hatts[1][vbase + 4 * k]);
                ar0 = ffma2(wr[0][k].x, hv.x, ar0); ar0 = ffma2(wr[0][k].y, hv.y, ar0);
                ar1 = ffma2(wr[1][k].x, hv.x, ar1); ar1 = ffma2(wr[1][k].y, hv.y, ar1);
            }
            R1 = redq2(ar0, ar1, hiRow);
        }

        const float xq = xs[p][s];
        const float ewq = ews[p][s];
        // lane roles: q0->rec(b0), q1->rec(b1), q2->ic(b0), q3->ic(b1)
        const float inB = (q & 2) ? fmaf(win, xq, bin) : ((p ? R1 : R0) + brec);
        const float tB = tanha(inB);
        const float icx = __shfl_xor_sync(0xffffffffu, tB, 2);  // q0<-ic0, q1<-ic1
        const float hn = hold + DT * ((icx + tB - hold) * itau) * (1.0f + ewq);
        if (q < 2) hs[p][hoff] = hn;             // q0 writes b0, q1 writes b1
        ewpq = ewq;
        __syncthreads();
    }

    // ---- trailing acc update: tanh(W_acc @ h_S) with ew_{S-1}
    {
        ull c00 = 0, c01 = 0, c10 = 0, c11 = 0;
#pragma unroll
        for (int k = 0; k < 4; k++) {
            const ulonglong2 h0 = *reinterpret_cast<const ulonglong2*>(&hs[0][vbase + 4 * k]);
            const ulonglong2 h1 = *reinterpret_cast<const ulonglong2*>(&hs[1][vbase + 4 * k]);
            c00 = ffma2(wc[0][k].x, h0.x, c00); c00 = ffma2(wc[0][k].y, h0.y, c00);
            c01 = ffma2(wc[1][k].x, h0.x, c01); c01 = ffma2(wc[1][k].y, h0.y, c01);
            c10 = ffma2(wc[0][k].x, h1.x, c10); c10 = ffma2(wc[0][k].y, h1.y, c10);
            c11 = ffma2(wc[1][k].x, h1.x, c11); c11 = ffma2(wc[1][k].y, h1.y, c11);
        }
        const float C0 = redq2(c00, c01, hiRow);
        const float C1 = redq2(c10, c11, hiRow);
        const float t = tanha((p ? C1 : C0) + pA_bias);  // valid on q2/q3 (bias=bacc)
        accq = 0.9f * accq + 0.1f * t * ewpq;
    }

    // ---- epilogue: out[b] = (h_f + acc_f) . W_out + b_out
    if (q & 2) hatts[p][hoff] = accq;   // q2 -> acc[b0], q3 -> acc[b1]
    __syncthreads();
    const int w = tid >> 5, l = tid & 31;
    if (w < NB) {
        float pacc = 0.0f;
#pragma unroll
        for (int i = 0; i < HH / 32; i++) {
            const int jo = i * PAD + l;
            pacc += (hs[w][jo] + hatts[w][jo]) * W_out[l + 32 * i];
        }
#pragma unroll
        for (int o = 16; o; o >>= 1) pacc += __shfl_xor_sync(0xffffffffu, pacc, o);
        if (l == 0) out[b0 + w] = pacc + b_out[0];
    }
}

extern "C" void kernel_launch(void* const* d_in, const int* in_sizes, int n_in,
                              void* d_out, int out_size) {
    const float* x     = (const float*)d_in[0];
    const float* W_in  = (const float*)d_in[1];
    const float* b_in  = (const float*)d_in[2];
    const float* W_rec = (const float*)d_in[3];
    const float* b_rec = (const float*)d_in[4];
    const float* tau   = (const float*)d_in[5];
    const float* W_att = (const float*)d_in[6];
    const float* b_att = (const float*)d_in[7];
    const float* W_ev  = (const float*)d_in[8];
    const float* b_ev  = (const float*)d_in[9];
    const float* W_acc = (const float*)d_in[10];
    const float* b_acc = (const float*)d_in[11];
    const float* W_out = (const float*)d_in[12];
    const float* b_out = (const float*)d_in[13];
    float* out = (float*)d_out;

    liquid_scan_kernel<<<BB / NB, NTHREADS>>>(x, W_in, b_in, W_rec, b_rec, tau,
                                              W_att, b_att, W_ev, b_ev,
                                              W_acc, b_acc, W_out, b_out, out);
}